// round 4
// baseline (speedup 1.0000x reference)
#include <cuda_runtime.h>
#include <cstdint>

#define Nn 100000
#define Ee 800000
typedef unsigned long long ull;

// ---------------- scratch (static __device__ globals; no runtime alloc) ----------------
__device__ int   g_is64;
__device__ int   g_degi[Nn];
__device__ float g_dinv[Nn];
__device__ float g_cinv[Nn];
__device__ int   g_rowptr[Nn + 1];
__device__ int   g_fill[Nn];
__device__ int   g_colidx[Ee];
__device__ float g_hA[(size_t)Nn * 256];
__device__ float g_hB[(size_t)Nn * 256];
__device__ float g_agg[(size_t)Nn * 256];

// ---------------- packed f32x2 helpers ----------------
__device__ __forceinline__ ull pack2(float x, float y) {
    ull r;
    asm("mov.b64 %0, {%1, %2};" : "=l"(r) : "f"(x), "f"(y));
    return r;
}
__device__ __forceinline__ void unpack2(ull v, float& x, float& y) {
    asm("mov.b64 {%0, %1}, %2;" : "=f"(x), "=f"(y) : "l"(v));
}
__device__ __forceinline__ ull ffma2(ull a, ull b, ull c) {
    ull d;
    asm("fma.rn.f32x2 %0, %1, %2, %3;" : "=l"(d) : "l"(a), "l"(b), "l"(c));
    return d;
}

// ---------------- dtype detection: int32 vs int64 edge_index ----------------
__global__ void k_detect(const int* __restrict__ w) {
    if (threadIdx.x == 0 && blockIdx.x == 0) {
        int is64 = 1;
        for (int i = 0; i < 256; i++)
            if (w[2 * i + 1] != 0) { is64 = 0; break; }
        g_is64 = is64;
    }
}

__device__ __forceinline__ int edge_at(const void* ei, int half, int e) {
    if (g_is64) return (int)((const long long*)ei)[(size_t)half * Ee + e];
    return ((const int*)ei)[(size_t)half * Ee + e];
}

// ---------------- small kernels ----------------
__global__ void k_zero(int* p, int n) {
    int i = blockIdx.x * blockDim.x + threadIdx.x;
    if (i < n) p[i] = 0;
}

__global__ void k_count(const void* __restrict__ ei, int* __restrict__ degi) {
    int e = blockIdx.x * blockDim.x + threadIdx.x;
    if (e < Ee) atomicAdd(&degi[edge_at(ei, 0, e)], 1);
}

__global__ void k_stats(const int* __restrict__ degi, float* __restrict__ dinv,
                        float* __restrict__ cinv) {
    int i = blockIdx.x * blockDim.x + threadIdx.x;
    if (i < Nn) {
        int d = degi[i];
        dinv[i] = (d > 0) ? rsqrtf((float)d) : 0.0f;
        cinv[i] = 1.0f / (float)max(d, 1);
    }
}

__global__ void k_scan(const int* __restrict__ cnt, int* __restrict__ rowptr,
                       int* __restrict__ fill) {
    __shared__ int wsum[32];
    __shared__ int carry;
    int tid = threadIdx.x, lane = tid & 31, wid = tid >> 5;
    if (tid == 0) carry = 0;
    __syncthreads();
    for (int base = 0; base < Nn; base += 1024) {
        int i = base + tid;
        int v = (i < Nn) ? cnt[i] : 0;
        int inc = v;
        #pragma unroll
        for (int o = 1; o < 32; o <<= 1) {
            int t = __shfl_up_sync(0xFFFFFFFFu, inc, o);
            if (lane >= o) inc += t;
        }
        if (lane == 31) wsum[wid] = inc;
        __syncthreads();
        if (wid == 0) {
            int s = wsum[lane];
            #pragma unroll
            for (int o = 1; o < 32; o <<= 1) {
                int t = __shfl_up_sync(0xFFFFFFFFu, s, o);
                if (lane >= o) s += t;
            }
            wsum[lane] = s;
        }
        __syncthreads();
        int woff  = wid ? wsum[wid - 1] : 0;
        int total = wsum[31];
        int ex = carry + woff + inc - v;
        if (i < Nn) { rowptr[i] = ex; fill[i] = ex; }
        __syncthreads();
        if (tid == 0) carry += total;
        __syncthreads();
    }
    if (threadIdx.x == 0) rowptr[Nn] = carry;
}

__global__ void k_fill(const void* __restrict__ ei, int* __restrict__ fill,
                       int* __restrict__ colidx) {
    int e = blockIdx.x * blockDim.x + threadIdx.x;
    if (e < Ee) {
        int r = edge_at(ei, 0, e);
        int c = edge_at(ei, 1, e);
        int p = atomicAdd(&fill[r], 1);
        colidx[p] = c;
    }
}

// ---------------- aggregation (CSR gather-sum) ----------------
template <int C, bool GCN>
__global__ void k_agg(const float* __restrict__ h, float* __restrict__ out,
                      const int* __restrict__ rowptr, const int* __restrict__ colidx,
                      const float* __restrict__ dinv, const float* __restrict__ cinv) {
    constexpr int TPN = C / 4;
    constexpr int NPB = 256 / TPN;
    int node = blockIdx.x * NPB + threadIdx.x / TPN;
    if (node >= Nn) return;
    int lane = threadIdx.x % TPN;
    int s = rowptr[node], e = rowptr[node + 1];
    const float4* h4 = (const float4*)h;
    float4 acc = make_float4(0.f, 0.f, 0.f, 0.f);
    for (int p = s; p < e; p++) {
        int j = colidx[p];
        float w = GCN ? dinv[j] : 1.0f;
        float4 v = __ldg(&h4[(size_t)j * TPN + lane]);
        acc.x += v.x * w; acc.y += v.y * w; acc.z += v.z * w; acc.w += v.w * w;
    }
    float sc = GCN ? dinv[node] : cinv[node];
    acc.x *= sc; acc.y *= sc; acc.z *= sc; acc.w *= sc;
    ((float4*)out)[(size_t)node * TPN + lane] = acc;
}

// ---------------- fused dual GEMM via packed f32x2 FFMA, 128x128 tile ----------------
// out = epi(A0@B0 [+ A1@B1] + bias); epi: relu or rezero-residual
#define BM 128
#define BN 128
#define BK 16
__global__ void __launch_bounds__(256, 2)
k_gemm(const float* __restrict__ A0, const float* __restrict__ B0,
       const float* __restrict__ A1, const float* __restrict__ B1,
       const float* __restrict__ bias,
       const float* __restrict__ res, const float* __restrict__ alphaPtr, int alphaIdx,
       float* __restrict__ out, int n, int K, int Cout, int doRelu) {
    __shared__ __align__(16) ull   sAp[BK][BM];   // A duplicated: (a,a) pairs, 16KB
    __shared__ __align__(16) float sB[BK][BN];    // 8KB
    int bm = blockIdx.y * BM;
    int bn = blockIdx.x * BN;
    int tx = threadIdx.x % 16;   // n-groups: cols tx*4..+3 and 64+tx*4..+3
    int ty = threadIdx.x / 16;   // m-group: rows ty*8..+7

    ull acc[8][4];
    #pragma unroll
    for (int i = 0; i < 8; i++)
        #pragma unroll
        for (int j = 0; j < 4; j++) acc[i][j] = 0ull;

    #pragma unroll 1
    for (int pass = 0; pass < 2; pass++) {
        const float* A = pass ? A1 : A0;
        const float* B = pass ? B1 : B0;
        if (!A) continue;
        #pragma unroll 1
        for (int k0 = 0; k0 < K; k0 += BK) {
            // A tile: 128 rows x 16 k; each thread loads 2 float4, stores duplicated pairs
            #pragma unroll
            for (int t = threadIdx.x; t < 512; t += 256) {
                int row = t / 4;
                int k4  = (t % 4) * 4;
                int gr = bm + row;
                float4 v = make_float4(0.f, 0.f, 0.f, 0.f);
                if (gr < n) v = *(const float4*)&A[(size_t)gr * K + k0 + k4];
                sAp[k4 + 0][row] = pack2(v.x, v.x);
                sAp[k4 + 1][row] = pack2(v.y, v.y);
                sAp[k4 + 2][row] = pack2(v.z, v.z);
                sAp[k4 + 3][row] = pack2(v.w, v.w);
            }
            // B tile: 16 k x 128 n; each thread loads 2 float4
            #pragma unroll
            for (int t = threadIdx.x; t < 512; t += 256) {
                int kk = t / 32;
                int n4 = (t % 32) * 4;
                int gc = bn + n4;
                float4 v = make_float4(0.f, 0.f, 0.f, 0.f);
                if (gc < Cout) v = *(const float4*)&B[(size_t)(k0 + kk) * Cout + gc];
                *(float4*)&sB[kk][n4] = v;
            }
            __syncthreads();
            #pragma unroll
            for (int kk = 0; kk < BK; kk++) {
                ulonglong2 bL = *(const ulonglong2*)&sB[kk][tx * 4];        // cols tx*4..+3
                ulonglong2 bH = *(const ulonglong2*)&sB[kk][64 + tx * 4];   // cols 64+tx*4..+3
                ulonglong2 a01 = *(const ulonglong2*)&sAp[kk][ty * 8 + 0];
                ulonglong2 a23 = *(const ulonglong2*)&sAp[kk][ty * 8 + 2];
                ulonglong2 a45 = *(const ulonglong2*)&sAp[kk][ty * 8 + 4];
                ulonglong2 a67 = *(const ulonglong2*)&sAp[kk][ty * 8 + 6];
                ull a[8] = {a01.x, a01.y, a23.x, a23.y, a45.x, a45.y, a67.x, a67.y};
                #pragma unroll
                for (int mi = 0; mi < 8; mi++) {
                    acc[mi][0] = ffma2(a[mi], bL.x, acc[mi][0]);
                    acc[mi][1] = ffma2(a[mi], bL.y, acc[mi][1]);
                    acc[mi][2] = ffma2(a[mi], bH.x, acc[mi][2]);
                    acc[mi][3] = ffma2(a[mi], bH.y, acc[mi][3]);
                }
            }
            __syncthreads();
        }
    }

    float alpha = alphaPtr ? __ldg(&alphaPtr[alphaIdx]) : 0.f;
    #pragma unroll
    for (int mi = 0; mi < 8; mi++) {
        int gr = bm + ty * 8 + mi;
        if (gr >= n) continue;
        #pragma unroll
        for (int half = 0; half < 2; half++) {
            int gc0 = bn + half * 64 + tx * 4;
            float v[4];
            unpack2(acc[mi][half * 2 + 0], v[0], v[1]);
            unpack2(acc[mi][half * 2 + 1], v[2], v[3]);
            if (gc0 + 3 < Cout) {
                float4 bv = *(const float4*)&bias[gc0];
                float4 o;
                o.x = v[0] + bv.x; o.y = v[1] + bv.y; o.z = v[2] + bv.z; o.w = v[3] + bv.w;
                if (doRelu) {
                    o.x = fmaxf(o.x, 0.f); o.y = fmaxf(o.y, 0.f);
                    o.z = fmaxf(o.z, 0.f); o.w = fmaxf(o.w, 0.f);
                }
                if (res) {
                    float4 rv = *(const float4*)&res[(size_t)gr * Cout + gc0];
                    o.x = rv.x + alpha * o.x; o.y = rv.y + alpha * o.y;
                    o.z = rv.z + alpha * o.z; o.w = rv.w + alpha * o.w;
                }
                *(float4*)&out[(size_t)gr * Cout + gc0] = o;
            } else {
                #pragma unroll
                for (int u = 0; u < 4; u++) {
                    int gc = gc0 + u;
                    if (gc >= Cout) continue;
                    float val = v[u] + __ldg(&bias[gc]);
                    if (doRelu) val = fmaxf(val, 0.f);
                    if (res) val = res[(size_t)gr * Cout + gc] + alpha * val;
                    out[(size_t)gr * Cout + gc] = val;
                }
            }
        }
    }
}

// ---------------- launch ----------------
extern "C" void kernel_launch(void* const* d_in, const int* in_sizes, int n_in,
                              void* d_out, int out_size) {
    const float* x     = (const float*)d_in[0];
    const void*  ei    = d_in[1];
    const float* alpha = (const float*)d_in[2];
    const float* W0 = (const float*)d_in[3];  const float* b0 = (const float*)d_in[4];
    const float* W1 = (const float*)d_in[5];  const float* R1 = (const float*)d_in[6];  const float* b1 = (const float*)d_in[7];
    const float* W2 = (const float*)d_in[8];  const float* R2 = (const float*)d_in[9];  const float* b2 = (const float*)d_in[10];
    const float* W3 = (const float*)d_in[11]; const float* b3 = (const float*)d_in[12];
    const float* W4 = (const float*)d_in[13]; const float* R4 = (const float*)d_in[14]; const float* b4 = (const float*)d_in[15];
    float* out = (float*)d_out;

    float *hA, *hB, *agg, *dinv, *cinv;
    int *degi, *rowptr, *fill, *colidx;
    cudaGetSymbolAddress((void**)&degi,   g_degi);
    cudaGetSymbolAddress((void**)&dinv,   g_dinv);
    cudaGetSymbolAddress((void**)&cinv,   g_cinv);
    cudaGetSymbolAddress((void**)&rowptr, g_rowptr);
    cudaGetSymbolAddress((void**)&fill,   g_fill);
    cudaGetSymbolAddress((void**)&colidx, g_colidx);
    cudaGetSymbolAddress((void**)&hA,     g_hA);
    cudaGetSymbolAddress((void**)&hB,     g_hB);
    cudaGetSymbolAddress((void**)&agg,    g_agg);

    const int NB_N = (Nn + 255) / 256;
    const int NB_E = (Ee + 255) / 256;
    const int MT   = (Nn + BM - 1) / BM;   // 782

    k_detect<<<1, 32>>>((const int*)ei);
    k_zero<<<NB_N, 256>>>(degi, Nn);
    k_count<<<NB_E, 256>>>(ei, degi);
    k_stats<<<NB_N, 256>>>(degi, dinv, cinv);
    k_scan<<<1, 1024>>>(degi, rowptr, fill);
    k_fill<<<NB_E, 256>>>(ei, fill, colidx);

    // layer 0: GCN, C=128, rezero residual (alpha[0])
    k_agg<128, true><<<Nn / 8, 256>>>(x, agg, rowptr, colidx, dinv, cinv);
    k_gemm<<<dim3(1, MT), 256>>>(agg, W0, nullptr, nullptr, b0, x, alpha, 0, hA, Nn, 128, 128, 0);

    // layer 1: SAGE 128->256 + relu
    k_agg<128, false><<<Nn / 8, 256>>>(hA, agg, rowptr, colidx, dinv, cinv);
    k_gemm<<<dim3(2, MT), 256>>>(agg, W1, hA, R1, b1, nullptr, nullptr, 0, hB, Nn, 128, 256, 1);

    // layer 2: SAGE 256->256 + relu
    k_agg<256, false><<<Nn / 4, 256>>>(hB, agg, rowptr, colidx, dinv, cinv);
    k_gemm<<<dim3(2, MT), 256>>>(agg, W2, hB, R2, b2, nullptr, nullptr, 0, hA, Nn, 256, 256, 1);

    // layer 3: GCN, C=256, rezero residual (alpha[3])
    k_agg<256, true><<<Nn / 4, 256>>>(hA, agg, rowptr, colidx, dinv, cinv);
    k_gemm<<<dim3(2, MT), 256>>>(agg, W3, nullptr, nullptr, b3, hA, alpha, 3, hB, Nn, 256, 256, 0);

    // layer 4: SAGE 256->112, no relu
    k_agg<256, false><<<Nn / 4, 256>>>(hB, agg, rowptr, colidx, dinv, cinv);
    k_gemm<<<dim3(1, MT), 256>>>(agg, W4, hB, R4, b4, nullptr, nullptr, 0, out, Nn, 256, 112, 0);
}